// round 1
// baseline (speedup 1.0000x reference)
#include <cuda_runtime.h>
#include <stdint.h>

#define NMAX   100000
#define CC     4
#define INCH   256
#define BGRAPH 64
#define SORTN  2048

// Scratch (device globals; no allocation allowed)
__device__ float g_xw[NMAX * CC];     // (x+pe_sum) @ W
__device__ float g_agg[NMAX * CC];    // edge aggregation -> becomes score
__device__ float g_dinv[NMAX];        // degree -> rsqrt(degree)
__device__ int   g_mask[NMAX];        // 4-bit selection mask per node

// ---------------------------------------------------------------------------
// Kernel 1: xw = (x + sum_c pools_emb[c]) @ W ; init deg=1, agg=0, mask=0
// warp per node, lane handles 8 features (2 x float4)
// ---------------------------------------------------------------------------
__global__ void k_xw(const float* __restrict__ x, const float* __restrict__ pe,
                     const float* __restrict__ W, int n) {
    __shared__ float  s_pes[INCH];
    __shared__ float4 s_W[INCH];          // W row k -> 4 floats
    int tid = threadIdx.x;
    for (int t = tid; t < INCH; t += blockDim.x) {
        s_pes[t] = pe[t] + pe[INCH + t] + pe[2 * INCH + t] + pe[3 * INCH + t];
        s_W[t]   = ((const float4*)W)[t];
    }
    __syncthreads();

    int gwarp = (blockIdx.x * blockDim.x + tid) >> 5;
    int lane  = tid & 31;
    if (gwarp >= n) return;

    const float4* xr = (const float4*)(x + (size_t)gwarp * INCH);
    float a0 = 0.f, a1 = 0.f, a2 = 0.f, a3 = 0.f;
#pragma unroll
    for (int it = 0; it < 2; ++it) {
        int k4 = lane + it * 32;          // float4 index 0..63
        float4 xv = xr[k4];
        int k = k4 * 4;
        float x0 = xv.x + s_pes[k + 0];
        float x1 = xv.y + s_pes[k + 1];
        float x2 = xv.z + s_pes[k + 2];
        float x3 = xv.w + s_pes[k + 3];
        float4 w0 = s_W[k + 0], w1 = s_W[k + 1], w2 = s_W[k + 2], w3 = s_W[k + 3];
        a0 += x0 * w0.x + x1 * w1.x + x2 * w2.x + x3 * w3.x;
        a1 += x0 * w0.y + x1 * w1.y + x2 * w2.y + x3 * w3.y;
        a2 += x0 * w0.z + x1 * w1.z + x2 * w2.z + x3 * w3.z;
        a3 += x0 * w0.w + x1 * w1.w + x2 * w2.w + x3 * w3.w;
    }
#pragma unroll
    for (int o = 16; o; o >>= 1) {
        a0 += __shfl_xor_sync(0xffffffffu, a0, o);
        a1 += __shfl_xor_sync(0xffffffffu, a1, o);
        a2 += __shfl_xor_sync(0xffffffffu, a2, o);
        a3 += __shfl_xor_sync(0xffffffffu, a3, o);
    }
    if (lane == 0) {
        ((float4*)g_xw)[gwarp]  = make_float4(a0, a1, a2, a3);
        ((float4*)g_agg)[gwarp] = make_float4(0.f, 0.f, 0.f, 0.f);
        g_dinv[gwarp] = 1.0f;             // self-loop counts as 1
        g_mask[gwarp] = 0;
    }
}

// ---------------------------------------------------------------------------
// Kernel 2: degree accumulation at col endpoints
// ---------------------------------------------------------------------------
__global__ void k_deg(const int* __restrict__ col, int E) {
    int e = blockIdx.x * blockDim.x + threadIdx.x;
    if (e < E) atomicAdd(&g_dinv[col[e]], 1.0f);
}

// ---------------------------------------------------------------------------
// Kernel 3: dinv = rsqrt(deg)
// ---------------------------------------------------------------------------
__global__ void k_rsqrt(int n) {
    int i = blockIdx.x * blockDim.x + threadIdx.x;
    if (i < n) g_dinv[i] = rsqrtf(g_dinv[i]);
}

// ---------------------------------------------------------------------------
// Kernel 4: edge aggregation  agg[col] += dinv[row]*dinv[col]*xw[row]
// vector red: 1 op per edge instead of 4 scalar atomics
// ---------------------------------------------------------------------------
__global__ void k_edge(const int* __restrict__ ei, int E) {
    int e = blockIdx.x * blockDim.x + threadIdx.x;
    if (e >= E) return;
    int r = ei[e];
    int c = ei[E + e];
    float nrm = g_dinv[r] * g_dinv[c];
    float4 v = ((const float4*)g_xw)[r];
    float v0 = nrm * v.x, v1 = nrm * v.y, v2 = nrm * v.z, v3 = nrm * v.w;
    asm volatile("red.global.add.v4.f32 [%0], {%1, %2, %3, %4};"
                 :: "l"(&g_agg[4 * c]), "f"(v0), "f"(v1), "f"(v2), "f"(v3)
                 : "memory");
}

// ---------------------------------------------------------------------------
// Kernel 5: score = tanh(agg + dinv^2 * xw + b)   (in place in g_agg)
// ---------------------------------------------------------------------------
__global__ void k_score(const float* __restrict__ b, int n) {
    int i = blockIdx.x * blockDim.x + threadIdx.x;
    if (i >= n) return;
    float d  = g_dinv[i];
    float d2 = d * d;
    float4 a  = ((const float4*)g_agg)[i];
    float4 xw = ((const float4*)g_xw)[i];
    a.x = tanhf(a.x + d2 * xw.x + b[0]);
    a.y = tanhf(a.y + d2 * xw.y + b[1]);
    a.z = tanhf(a.z + d2 * xw.z + b[2]);
    a.w = tanhf(a.w + d2 * xw.w + b[3]);
    ((float4*)g_agg)[i] = a;
}

// ---------------------------------------------------------------------------
// Kernel 6: per (graph, column) top-k via bitonic sort in shared memory.
// Key = (~orderable(score) << 32) | local_index : ascending 64-bit sort gives
// descending score with ascending-index tie-break == jax stable lexsort.
// ---------------------------------------------------------------------------
__global__ void k_topk(const int* __restrict__ batch, int n) {
    __shared__ unsigned long long keys[SORTN];
    __shared__ int s_bounds[2];
    int g = blockIdx.x >> 2;
    int c = blockIdx.x & 3;

    if (threadIdx.x == 0) {
        int lo = 0, hi = n;
        while (lo < hi) { int m = (lo + hi) >> 1; if (batch[m] < g) lo = m + 1; else hi = m; }
        s_bounds[0] = lo;
        hi = n;
        while (lo < hi) { int m = (lo + hi) >> 1; if (batch[m] < g + 1) lo = m + 1; else hi = m; }
        s_bounds[1] = lo;
    }
    __syncthreads();
    int start = s_bounds[0];
    int ng    = s_bounds[1] - s_bounds[0];
    int k     = (ng + 1) >> 1;            // ceil(0.5 * ng)
    if (k == 0) return;

    if (ng <= SORTN) {
        for (int t = threadIdx.x; t < SORTN; t += blockDim.x) {
            unsigned long long key;
            if (t < ng) {
                float s = g_agg[(size_t)(start + t) * 4 + c];
                unsigned u = __float_as_uint(s);
                u = (u & 0x80000000u) ? ~u : (u | 0x80000000u);  // ascending order map
                u = ~u;                                           // descending
                key = ((unsigned long long)u << 32) | (unsigned)t;
            } else {
                key = 0xFFFFFFFFFFFFFFFFull;                      // pads sort last
            }
            keys[t] = key;
        }
        __syncthreads();
        for (int kk = 2; kk <= SORTN; kk <<= 1) {
            for (int j = kk >> 1; j > 0; j >>= 1) {
                for (int i = threadIdx.x; i < SORTN; i += blockDim.x) {
                    int ixj = i ^ j;
                    if (ixj > i) {
                        bool up = (i & kk) == 0;
                        unsigned long long a = keys[i], bq = keys[ixj];
                        if ((a > bq) == up) { keys[i] = bq; keys[ixj] = a; }
                    }
                }
                __syncthreads();
            }
        }
        for (int r = threadIdx.x; r < k; r += blockDim.x) {
            int loc = (int)(keys[r] & 0xFFFFFFFFu);
            atomicOr(&g_mask[start + loc], 1 << c);
        }
    } else {
        // Fallback (never expected at these sizes): O(n^2) exact ranking
        for (int t = threadIdx.x; t < ng; t += blockDim.x) {
            float st = g_agg[(size_t)(start + t) * 4 + c];
            int rank = 0;
            for (int j = 0; j < ng; ++j) {
                float sj = g_agg[(size_t)(start + j) * 4 + c];
                rank += (sj > st) || (sj == st && j < t);
            }
            if (rank < k) atomicOr(&g_mask[start + t], 1 << c);
        }
    }
}

// ---------------------------------------------------------------------------
// Kernel 7: out = x + ((mask*score) @ pools_emb) / (1 + popc(mask))
// warp per node, lane handles 8 features
// ---------------------------------------------------------------------------
__global__ void k_out(const float* __restrict__ x, const float* __restrict__ pe,
                      float* __restrict__ out, int n) {
    __shared__ float4 s_pe[CC * (INCH / 4)];
    int tid = threadIdx.x;
    for (int t = tid; t < CC * (INCH / 4); t += blockDim.x)
        s_pe[t] = ((const float4*)pe)[t];
    __syncthreads();

    int gwarp = (blockIdx.x * blockDim.x + tid) >> 5;
    int lane  = tid & 31;
    if (gwarp >= n) return;

    int   m   = g_mask[gwarp];
    float inv = 1.0f / (1.0f + (float)__popc(m & 0xF));
    float4 s  = ((const float4*)g_agg)[gwarp];
    float w0 = (m & 1) ? s.x * inv : 0.f;
    float w1 = (m & 2) ? s.y * inv : 0.f;
    float w2 = (m & 4) ? s.z * inv : 0.f;
    float w3 = (m & 8) ? s.w * inv : 0.f;

    const float4* xr   = (const float4*)(x + (size_t)gwarp * INCH);
    float4*       orow = (float4*)(out + (size_t)gwarp * INCH);
#pragma unroll
    for (int it = 0; it < 2; ++it) {
        int k4 = lane + it * 32;
        float4 xv = xr[k4];
        float4 p0 = s_pe[0 * 64 + k4];
        float4 p1 = s_pe[1 * 64 + k4];
        float4 p2 = s_pe[2 * 64 + k4];
        float4 p3 = s_pe[3 * 64 + k4];
        float4 o;
        o.x = xv.x + w0 * p0.x + w1 * p1.x + w2 * p2.x + w3 * p3.x;
        o.y = xv.y + w0 * p0.y + w1 * p1.y + w2 * p2.y + w3 * p3.y;
        o.z = xv.z + w0 * p0.z + w1 * p1.z + w2 * p2.z + w3 * p3.z;
        o.w = xv.w + w0 * p0.w + w1 * p1.w + w2 * p2.w + w3 * p3.w;
        orow[k4] = o;
    }
}

// ---------------------------------------------------------------------------
extern "C" void kernel_launch(void* const* d_in, const int* in_sizes, int n_in,
                              void* d_out, int out_size) {
    const float* x     = (const float*)d_in[0];
    const int*   ei    = (const int*)  d_in[1];
    const int*   batch = (const int*)  d_in[2];
    const float* pe    = (const float*)d_in[3];
    const float* W     = (const float*)d_in[4];
    const float* b     = (const float*)d_in[5];
    float*       out   = (float*)d_out;

    int n = in_sizes[0] / INCH;
    int E = in_sizes[1] / 2;

    int warpBlocks = (n + 7) / 8;               // 8 warps (nodes) per 256-thread block
    k_xw   <<<warpBlocks, 256>>>(x, pe, W, n);
    k_deg  <<<(E + 255) / 256, 256>>>(ei + E, E);
    k_rsqrt<<<(n + 255) / 256, 256>>>(n);
    k_edge <<<(E + 255) / 256, 256>>>(ei, E);
    k_score<<<(n + 255) / 256, 256>>>(b, n);
    k_topk <<<BGRAPH * CC, 1024>>>(batch, n);
    k_out  <<<warpBlocks, 256>>>(x, pe, out, n);
}

// round 3
// speedup vs baseline: 1.0692x; 1.0692x over previous
#include <cuda_runtime.h>
#include <stdint.h>

#define NMAX   100000
#define CC     4
#define INCH   256
#define BGRAPH 64
#define SORTN  2048
#define TK_NT  256

// Scratch (device globals; no allocation allowed)
__device__ float g_xw[NMAX * CC];     // (x+pe_sum) @ W
__device__ float g_agg[NMAX * CC];    // edge aggregation -> becomes score
__device__ float g_dinv[NMAX];        // degree -> rsqrt(degree)
__device__ int   g_mask[NMAX];        // 4-bit selection mask per node

// ---------------------------------------------------------------------------
// Kernel 1: xw = (x + sum_c pools_emb[c]) @ W ; init deg=1, agg=0, mask=0
// warp per node, lane handles 8 features (2 x float4)
// ---------------------------------------------------------------------------
__global__ void k_xw(const float* __restrict__ x, const float* __restrict__ pe,
                     const float* __restrict__ W, int n) {
    __shared__ float  s_pes[INCH];
    __shared__ float4 s_W[INCH];          // W row k -> 4 floats
    int tid = threadIdx.x;
    for (int t = tid; t < INCH; t += blockDim.x) {
        s_pes[t] = pe[t] + pe[INCH + t] + pe[2 * INCH + t] + pe[3 * INCH + t];
        s_W[t]   = ((const float4*)W)[t];
    }
    __syncthreads();

    int gwarp = (blockIdx.x * blockDim.x + tid) >> 5;
    int lane  = tid & 31;
    if (gwarp >= n) return;

    const float4* xr = (const float4*)(x + (size_t)gwarp * INCH);
    float a0 = 0.f, a1 = 0.f, a2 = 0.f, a3 = 0.f;
#pragma unroll
    for (int it = 0; it < 2; ++it) {
        int k4 = lane + it * 32;          // float4 index 0..63
        float4 xv = xr[k4];
        int k = k4 * 4;
        float x0 = xv.x + s_pes[k + 0];
        float x1 = xv.y + s_pes[k + 1];
        float x2 = xv.z + s_pes[k + 2];
        float x3 = xv.w + s_pes[k + 3];
        float4 w0 = s_W[k + 0], w1 = s_W[k + 1], w2 = s_W[k + 2], w3 = s_W[k + 3];
        a0 += x0 * w0.x + x1 * w1.x + x2 * w2.x + x3 * w3.x;
        a1 += x0 * w0.y + x1 * w1.y + x2 * w2.y + x3 * w3.y;
        a2 += x0 * w0.z + x1 * w1.z + x2 * w2.z + x3 * w3.z;
        a3 += x0 * w0.w + x1 * w1.w + x2 * w2.w + x3 * w3.w;
    }
#pragma unroll
    for (int o = 16; o; o >>= 1) {
        a0 += __shfl_xor_sync(0xffffffffu, a0, o);
        a1 += __shfl_xor_sync(0xffffffffu, a1, o);
        a2 += __shfl_xor_sync(0xffffffffu, a2, o);
        a3 += __shfl_xor_sync(0xffffffffu, a3, o);
    }
    if (lane == 0) {
        ((float4*)g_xw)[gwarp]  = make_float4(a0, a1, a2, a3);
        ((float4*)g_agg)[gwarp] = make_float4(0.f, 0.f, 0.f, 0.f);
        g_dinv[gwarp] = 1.0f;             // self-loop counts as 1
        g_mask[gwarp] = 0;
    }
}

// ---------------------------------------------------------------------------
// Kernel 2: degree accumulation at col endpoints
// ---------------------------------------------------------------------------
__global__ void k_deg(const int* __restrict__ col, int E) {
    int e = blockIdx.x * blockDim.x + threadIdx.x;
    if (e < E) atomicAdd(&g_dinv[col[e]], 1.0f);
}

// ---------------------------------------------------------------------------
// Kernel 3: dinv = rsqrt(deg)
// ---------------------------------------------------------------------------
__global__ void k_rsqrt(int n) {
    int i = blockIdx.x * blockDim.x + threadIdx.x;
    if (i < n) g_dinv[i] = rsqrtf(g_dinv[i]);
}

// ---------------------------------------------------------------------------
// Kernel 4: edge aggregation  agg[col] += dinv[row]*dinv[col]*xw[row]
// 2 edges per thread, loads front-batched for MLP against L2 latency
// ---------------------------------------------------------------------------
__global__ void k_edge(const int* __restrict__ ei, int E) {
    int t = blockIdx.x * blockDim.x + threadIdx.x;
    int half = (E + 1) >> 1;
    int e0 = t;
    int e1 = t + half;
    if (e0 >= E) return;
    bool has1 = (e1 < E);

    int r0 = ei[e0];
    int c0 = ei[E + e0];
    int r1 = has1 ? ei[e1] : r0;
    int c1 = has1 ? ei[E + e1] : c0;

    float dr0 = g_dinv[r0], dc0 = g_dinv[c0];
    float dr1 = g_dinv[r1], dc1 = g_dinv[c1];
    float4 v0 = ((const float4*)g_xw)[r0];
    float4 v1 = ((const float4*)g_xw)[r1];

    float n0 = dr0 * dc0;
    float a0 = n0 * v0.x, a1 = n0 * v0.y, a2 = n0 * v0.z, a3 = n0 * v0.w;
    asm volatile("red.global.add.v4.f32 [%0], {%1, %2, %3, %4};"
                 :: "l"(&g_agg[4 * c0]), "f"(a0), "f"(a1), "f"(a2), "f"(a3)
                 : "memory");
    if (has1) {
        float n1 = dr1 * dc1;
        float b0 = n1 * v1.x, b1 = n1 * v1.y, b2 = n1 * v1.z, b3 = n1 * v1.w;
        asm volatile("red.global.add.v4.f32 [%0], {%1, %2, %3, %4};"
                     :: "l"(&g_agg[4 * c1]), "f"(b0), "f"(b1), "f"(b2), "f"(b3)
                     : "memory");
    }
}

// ---------------------------------------------------------------------------
// Kernel 5: score = tanh(agg + dinv^2 * xw + b)   (in place in g_agg)
// ---------------------------------------------------------------------------
__global__ void k_score(const float* __restrict__ b, int n) {
    int i = blockIdx.x * blockDim.x + threadIdx.x;
    if (i >= n) return;
    float d  = g_dinv[i];
    float d2 = d * d;
    float4 a  = ((const float4*)g_agg)[i];
    float4 xw = ((const float4*)g_xw)[i];
    a.x = tanhf(a.x + d2 * xw.x + b[0]);
    a.y = tanhf(a.y + d2 * xw.y + b[1]);
    a.z = tanhf(a.z + d2 * xw.z + b[2]);
    a.w = tanhf(a.w + d2 * xw.w + b[3]);
    ((float4*)g_agg)[i] = a;
}

// ---------------------------------------------------------------------------
// Kernel 6: per (graph, column) top-k via MSB radix select (4 byte passes)
// over a 32-bit key u = ~orderable(score): ascending u == descending score.
// Ties (equal score bits) resolved by smallest local index == jax stable
// lexsort. Fallback O(n^2) path for ng > SORTN (never expected here).
// ---------------------------------------------------------------------------
__global__ void k_topk(const int* __restrict__ batch, int n) {
    __shared__ unsigned s_u[SORTN];
    __shared__ int s_hist[256];
    __shared__ int s_cnt[TK_NT + 1];
    __shared__ int s_bounds[2];
    __shared__ unsigned s_prefix;
    __shared__ int s_target;

    int g = blockIdx.x >> 2;
    int c = blockIdx.x & 3;
    int tid = threadIdx.x;

    if (tid == 0) {
        int lo = 0, hi = n;
        while (lo < hi) { int m = (lo + hi) >> 1; if (batch[m] < g) lo = m + 1; else hi = m; }
        s_bounds[0] = lo;
        hi = n;
        while (lo < hi) { int m = (lo + hi) >> 1; if (batch[m] < g + 1) lo = m + 1; else hi = m; }
        s_bounds[1] = lo;
        s_prefix = 0u;
    }
    __syncthreads();
    int start = s_bounds[0];
    int ng    = s_bounds[1] - s_bounds[0];
    int k     = (ng + 1) >> 1;            // ceil(0.5 * ng)
    if (k == 0) return;

    if (ng <= SORTN) {
        // load + transform to "ascending = selected first" key
        for (int t = tid; t < ng; t += TK_NT) {
            unsigned u = __float_as_uint(g_agg[(size_t)(start + t) * 4 + c]);
            u = (u & 0x80000000u) ? ~u : (u | 0x80000000u);  // ascending float order
            s_u[t] = ~u;                                      // descending score
        }
        if (tid == 0) s_target = k - 1;   // 0-based rank of threshold key
        __syncthreads();

        // 4 MSB->LSB byte passes
        unsigned done_mask = 0u;
#pragma unroll
        for (int pass = 0; pass < 4; ++pass) {
            int shift = 24 - 8 * pass;
            s_hist[tid & 255] = 0;        // TK_NT == 256
            __syncthreads();
            unsigned pref = s_prefix;
            for (int t = tid; t < ng; t += TK_NT) {
                unsigned u = s_u[t];
                if ((u & done_mask) == pref)
                    atomicAdd(&s_hist[(u >> shift) & 255u], 1);
            }
            __syncthreads();
            if (tid == 0) {
                int cum = 0, tgt = s_target;
                for (int bn = 0; bn < 256; ++bn) {
                    int h = s_hist[bn];
                    if (cum + h > tgt) {
                        s_prefix |= ((unsigned)bn) << shift;
                        s_target = tgt - cum;
                        break;
                    }
                    cum += h;
                }
            }
            done_mask |= 0xFFu << shift;
            __syncthreads();
        }
        unsigned T = s_prefix;            // threshold key (k-th in ascending order)
        int r = s_target;                 // stable rank among equals to also select

        // stable tie ranking: chunked exclusive count of (u == T)
        int chunk = (ng + TK_NT - 1) / TK_NT;
        int lo = tid * chunk;
        int hi = min(lo + chunk, ng);
        int cnt = 0;
        for (int t = lo; t < hi; ++t) cnt += (s_u[t] == T);
        s_cnt[tid] = cnt;
        __syncthreads();
        if (tid == 0) {
            int run = 0;
            for (int i = 0; i < TK_NT; ++i) { int v = s_cnt[i]; s_cnt[i] = run; run += v; }
        }
        __syncthreads();
        int eqrank = s_cnt[tid];
        for (int t = lo; t < hi; ++t) {
            unsigned u = s_u[t];
            bool sel = (u < T) || (u == T && eqrank <= r);
            eqrank += (u == T);
            if (sel) atomicOr(&g_mask[start + t], 1 << c);
        }
    } else {
        // Fallback (never expected at these sizes): O(n^2) exact ranking
        for (int t = tid; t < ng; t += TK_NT) {
            float st = g_agg[(size_t)(start + t) * 4 + c];
            int rank = 0;
            for (int j = 0; j < ng; ++j) {
                float sj = g_agg[(size_t)(start + j) * 4 + c];
                rank += (sj > st) || (sj == st && j < t);
            }
            if (rank < k) atomicOr(&g_mask[start + t], 1 << c);
        }
    }
}

// ---------------------------------------------------------------------------
// Kernel 7: out = x + ((mask*score) @ pools_emb) / (1 + popc(mask))
// warp per node, lane handles 8 features
// ---------------------------------------------------------------------------
__global__ void k_out(const float* __restrict__ x, const float* __restrict__ pe,
                      float* __restrict__ out, int n) {
    __shared__ float4 s_pe[CC * (INCH / 4)];
    int tid = threadIdx.x;
    for (int t = tid; t < CC * (INCH / 4); t += blockDim.x)
        s_pe[t] = ((const float4*)pe)[t];
    __syncthreads();

    int gwarp = (blockIdx.x * blockDim.x + tid) >> 5;
    int lane  = tid & 31;
    if (gwarp >= n) return;

    int   m   = g_mask[gwarp];
    float inv = 1.0f / (1.0f + (float)__popc(m & 0xF));
    float4 s  = ((const float4*)g_agg)[gwarp];
    float w0 = (m & 1) ? s.x * inv : 0.f;
    float w1 = (m & 2) ? s.y * inv : 0.f;
    float w2 = (m & 4) ? s.z * inv : 0.f;
    float w3 = (m & 8) ? s.w * inv : 0.f;

    const float4* xr   = (const float4*)(x + (size_t)gwarp * INCH);
    float4*       orow = (float4*)(out + (size_t)gwarp * INCH);
#pragma unroll
    for (int it = 0; it < 2; ++it) {
        int k4 = lane + it * 32;
        float4 xv = xr[k4];
        float4 p0 = s_pe[0 * 64 + k4];
        float4 p1 = s_pe[1 * 64 + k4];
        float4 p2 = s_pe[2 * 64 + k4];
        float4 p3 = s_pe[3 * 64 + k4];
        float4 o;
        o.x = xv.x + w0 * p0.x + w1 * p1.x + w2 * p2.x + w3 * p3.x;
        o.y = xv.y + w0 * p0.y + w1 * p1.y + w2 * p2.y + w3 * p3.y;
        o.z = xv.z + w0 * p0.z + w1 * p1.z + w2 * p2.z + w3 * p3.z;
        o.w = xv.w + w0 * p0.w + w1 * p1.w + w2 * p2.w + w3 * p3.w;
        orow[k4] = o;
    }
}

// ---------------------------------------------------------------------------
extern "C" void kernel_launch(void* const* d_in, const int* in_sizes, int n_in,
                              void* d_out, int out_size) {
    const float* x     = (const float*)d_in[0];
    const int*   ei    = (const int*)  d_in[1];
    const int*   batch = (const int*)  d_in[2];
    const float* pe    = (const float*)d_in[3];
    const float* W     = (const float*)d_in[4];
    const float* b     = (const float*)d_in[5];
    float*       out   = (float*)d_out;

    int n = in_sizes[0] / INCH;
    int E = in_sizes[1] / 2;
    int halfE = (E + 1) >> 1;

    int warpBlocks = (n + 7) / 8;               // 8 warps (nodes) per 256-thread block
    k_xw   <<<warpBlocks, 256>>>(x, pe, W, n);
    k_deg  <<<(E + 255) / 256, 256>>>(ei + E, E);
    k_rsqrt<<<(n + 255) / 256, 256>>>(n);
    k_edge <<<(halfE + 255) / 256, 256>>>(ei, E);
    k_score<<<(n + 255) / 256, 256>>>(b, n);
    k_topk <<<BGRAPH * CC, TK_NT>>>(batch, n);
    k_out  <<<warpBlocks, 256>>>(x, pe, out, n);
}

// round 4
// speedup vs baseline: 1.2534x; 1.1722x over previous
#include <cuda_runtime.h>
#include <stdint.h>

#define NMAX   100000
#define CC     4
#define INCH   256
#define BGRAPH 64
#define SORTN  2048
#define TK_NT  256

// Scratch (device globals; no allocation allowed)
__device__ float g_xw[NMAX * CC];     // (x+pe_sum)@W, then premultiplied by dinv
__device__ float g_agg[NMAX * CC];    // raw edge aggregation -> becomes score
__device__ float g_dinv[NMAX];        // degree -> rsqrt(degree)
__device__ int   g_mask[NMAX];        // 4-bit selection mask per node

// ---------------------------------------------------------------------------
// Kernel 1: xw = (x + sum_c pools_emb[c]) @ W ; init deg=1, agg=0, mask=0
// warp per node, lane handles 8 features (2 x float4)
// ---------------------------------------------------------------------------
__global__ void k_xw(const float* __restrict__ x, const float* __restrict__ pe,
                     const float* __restrict__ W, int n) {
    __shared__ float  s_pes[INCH];
    __shared__ float4 s_W[INCH];          // W row k -> 4 floats
    int tid = threadIdx.x;
    for (int t = tid; t < INCH; t += blockDim.x) {
        s_pes[t] = pe[t] + pe[INCH + t] + pe[2 * INCH + t] + pe[3 * INCH + t];
        s_W[t]   = ((const float4*)W)[t];
    }
    __syncthreads();

    int gwarp = (blockIdx.x * blockDim.x + tid) >> 5;
    int lane  = tid & 31;
    if (gwarp >= n) return;

    const float4* xr = (const float4*)(x + (size_t)gwarp * INCH);
    float a0 = 0.f, a1 = 0.f, a2 = 0.f, a3 = 0.f;
#pragma unroll
    for (int it = 0; it < 2; ++it) {
        int k4 = lane + it * 32;          // float4 index 0..63
        float4 xv = xr[k4];
        int k = k4 * 4;
        float x0 = xv.x + s_pes[k + 0];
        float x1 = xv.y + s_pes[k + 1];
        float x2 = xv.z + s_pes[k + 2];
        float x3 = xv.w + s_pes[k + 3];
        float4 w0 = s_W[k + 0], w1 = s_W[k + 1], w2 = s_W[k + 2], w3 = s_W[k + 3];
        a0 += x0 * w0.x + x1 * w1.x + x2 * w2.x + x3 * w3.x;
        a1 += x0 * w0.y + x1 * w1.y + x2 * w2.y + x3 * w3.y;
        a2 += x0 * w0.z + x1 * w1.z + x2 * w2.z + x3 * w3.z;
        a3 += x0 * w0.w + x1 * w1.w + x2 * w2.w + x3 * w3.w;
    }
#pragma unroll
    for (int o = 16; o; o >>= 1) {
        a0 += __shfl_xor_sync(0xffffffffu, a0, o);
        a1 += __shfl_xor_sync(0xffffffffu, a1, o);
        a2 += __shfl_xor_sync(0xffffffffu, a2, o);
        a3 += __shfl_xor_sync(0xffffffffu, a3, o);
    }
    if (lane == 0) {
        ((float4*)g_xw)[gwarp]  = make_float4(a0, a1, a2, a3);
        ((float4*)g_agg)[gwarp] = make_float4(0.f, 0.f, 0.f, 0.f);
        g_dinv[gwarp] = 1.0f;             // self-loop counts as 1
        g_mask[gwarp] = 0;
    }
}

// ---------------------------------------------------------------------------
// Kernel 2: degree accumulation at col endpoints
// ---------------------------------------------------------------------------
__global__ void k_deg(const int* __restrict__ col, int E) {
    int e = blockIdx.x * blockDim.x + threadIdx.x;
    if (e < E) atomicAdd(&g_dinv[col[e]], 1.0f);
}

// ---------------------------------------------------------------------------
// Kernel 3: dinv = rsqrt(deg); premultiply xw by dinv (xws = dinv * xw)
// ---------------------------------------------------------------------------
__global__ void k_prep(int n) {
    int i = blockIdx.x * blockDim.x + threadIdx.x;
    if (i >= n) return;
    float d = rsqrtf(g_dinv[i]);
    g_dinv[i] = d;
    float4 v = ((const float4*)g_xw)[i];
    v.x *= d; v.y *= d; v.z *= d; v.w *= d;
    ((float4*)g_xw)[i] = v;
}

// ---------------------------------------------------------------------------
// Kernel 4: edge aggregation  agg[col] += xws[row]   (dinv[col] applied later)
// 4 edges per thread, loads front-batched for MLP against L2 latency
// ---------------------------------------------------------------------------
__global__ void k_edge(const int* __restrict__ ei, int E) {
    int t = blockIdx.x * blockDim.x + threadIdx.x;
    int quarter = (E + 3) >> 2;
    int e0 = t;
    if (e0 >= quarter) return;
    int e1 = e0 + quarter, e2 = e0 + 2 * quarter, e3 = e0 + 3 * quarter;
    bool h1 = e1 < E, h2 = e2 < E, h3 = e3 < E;

    int r0 = ei[e0];
    int r1 = h1 ? ei[e1] : r0;
    int r2 = h2 ? ei[e2] : r0;
    int r3 = h3 ? ei[e3] : r0;
    int c0 = ei[E + e0];
    int c1 = h1 ? ei[E + e1] : c0;
    int c2 = h2 ? ei[E + e2] : c0;
    int c3 = h3 ? ei[E + e3] : c0;

    float4 v0 = ((const float4*)g_xw)[r0];
    float4 v1 = ((const float4*)g_xw)[r1];
    float4 v2 = ((const float4*)g_xw)[r2];
    float4 v3 = ((const float4*)g_xw)[r3];

    asm volatile("red.global.add.v4.f32 [%0], {%1, %2, %3, %4};"
                 :: "l"(&g_agg[4 * c0]), "f"(v0.x), "f"(v0.y), "f"(v0.z), "f"(v0.w)
                 : "memory");
    if (h1)
        asm volatile("red.global.add.v4.f32 [%0], {%1, %2, %3, %4};"
                     :: "l"(&g_agg[4 * c1]), "f"(v1.x), "f"(v1.y), "f"(v1.z), "f"(v1.w)
                     : "memory");
    if (h2)
        asm volatile("red.global.add.v4.f32 [%0], {%1, %2, %3, %4};"
                     :: "l"(&g_agg[4 * c2]), "f"(v2.x), "f"(v2.y), "f"(v2.z), "f"(v2.w)
                     : "memory");
    if (h3)
        asm volatile("red.global.add.v4.f32 [%0], {%1, %2, %3, %4};"
                     :: "l"(&g_agg[4 * c3]), "f"(v3.x), "f"(v3.y), "f"(v3.z), "f"(v3.w)
                     : "memory");
}

// ---------------------------------------------------------------------------
// Kernel 5: score = tanh(dinv*(agg_raw + xws) + b)   (in place in g_agg)
//   dinv*agg_raw == edge term;  dinv*xws == dinv^2*xw self-loop term
// ---------------------------------------------------------------------------
__global__ void k_score(const float* __restrict__ b, int n) {
    int i = blockIdx.x * blockDim.x + threadIdx.x;
    if (i >= n) return;
    float d  = g_dinv[i];
    float4 a  = ((const float4*)g_agg)[i];
    float4 xw = ((const float4*)g_xw)[i];
    a.x = tanhf(d * (a.x + xw.x) + b[0]);
    a.y = tanhf(d * (a.y + xw.y) + b[1]);
    a.z = tanhf(d * (a.z + xw.z) + b[2]);
    a.w = tanhf(d * (a.w + xw.w) + b[3]);
    ((float4*)g_agg)[i] = a;
}

// ---------------------------------------------------------------------------
// Block-wide exclusive scan of 256 ints held one-per-thread (TK_NT == 256).
// Returns exclusive prefix; also writes total via pointer if needed.
// ---------------------------------------------------------------------------
__device__ __forceinline__ int block_excl_scan_256(int v, int tid, int* s_wsum) {
    int lane = tid & 31, wid = tid >> 5;
    int orig = v;
#pragma unroll
    for (int o = 1; o < 32; o <<= 1) {
        int t = __shfl_up_sync(0xffffffffu, v, o);
        if (lane >= o) v += t;
    }
    if (lane == 31) s_wsum[wid] = v;
    __syncthreads();
    if (wid == 0 && lane < 8) {
        int w = s_wsum[lane];
#pragma unroll
        for (int o = 1; o < 8; o <<= 1) {
            int t = __shfl_up_sync(0xffu, w, o);
            if (lane >= o) w += t;
        }
        s_wsum[lane] = w;
    }
    __syncthreads();
    int incl = v + (wid ? s_wsum[wid - 1] : 0);
    return incl - orig;
}

// ---------------------------------------------------------------------------
// Kernel 6: per (graph, column) top-k via MSB radix select (4 byte passes)
// over 32-bit key u = ~orderable(score): ascending u == descending score.
// Ties resolved by smallest index == jax stable lexsort.
// ---------------------------------------------------------------------------
__global__ void k_topk(const int* __restrict__ batch, int n) {
    __shared__ unsigned s_u[SORTN];
    __shared__ int s_hist[256];
    __shared__ int s_wsum[8];
    __shared__ int s_bounds[2];
    __shared__ unsigned s_prefix;
    __shared__ int s_target;

    int g = blockIdx.x >> 2;
    int c = blockIdx.x & 3;
    int tid = threadIdx.x;

    if (tid == 0) {
        int lo = 0, hi = n;
        while (lo < hi) { int m = (lo + hi) >> 1; if (batch[m] < g) lo = m + 1; else hi = m; }
        s_bounds[0] = lo;
        hi = n;
        while (lo < hi) { int m = (lo + hi) >> 1; if (batch[m] < g + 1) lo = m + 1; else hi = m; }
        s_bounds[1] = lo;
        s_prefix = 0u;
    }
    __syncthreads();
    int start = s_bounds[0];
    int ng    = s_bounds[1] - s_bounds[0];
    int k     = (ng + 1) >> 1;            // ceil(0.5 * ng)
    if (k == 0) return;

    if (ng <= SORTN) {
        for (int t = tid; t < ng; t += TK_NT) {
            unsigned u = __float_as_uint(g_agg[(size_t)(start + t) * 4 + c]);
            u = (u & 0x80000000u) ? ~u : (u | 0x80000000u);  // ascending float order
            s_u[t] = ~u;                                      // descending score
        }
        if (tid == 0) s_target = k - 1;   // 0-based rank of threshold key
        __syncthreads();

        unsigned done_mask = 0u;
#pragma unroll
        for (int pass = 0; pass < 4; ++pass) {
            int shift = 24 - 8 * pass;
            s_hist[tid] = 0;
            __syncthreads();
            unsigned pref = s_prefix;
            int tgt = s_target;
            for (int t = tid; t < ng; t += TK_NT) {
                unsigned u = s_u[t];
                if ((u & done_mask) == pref)
                    atomicAdd(&s_hist[(u >> shift) & 255u], 1);
            }
            __syncthreads();
            int h    = s_hist[tid];
            int excl = block_excl_scan_256(h, tid, s_wsum);
            if (excl <= tgt && tgt < excl + h) {
                s_prefix |= ((unsigned)tid) << shift;
                s_target = tgt - excl;
            }
            done_mask |= 0xFFu << shift;
            __syncthreads();
        }
        unsigned T = s_prefix;            // threshold key
        int r = s_target;                 // rank among equals still selected

        // stable tie ranking: chunked exclusive count of (u == T)
        int chunk = (ng + TK_NT - 1) / TK_NT;
        int lo = min(tid * chunk, ng);
        int hi = min(lo + chunk, ng);
        int cnt = 0;
        for (int t = lo; t < hi; ++t) cnt += (s_u[t] == T);
        int eqrank = block_excl_scan_256(cnt, tid, s_wsum);
        for (int t = lo; t < hi; ++t) {
            unsigned u = s_u[t];
            bool sel = (u < T) || (u == T && eqrank <= r);
            eqrank += (u == T);
            if (sel) atomicOr(&g_mask[start + t], 1 << c);
        }
    } else {
        // Fallback (never expected at these sizes): O(n^2) exact ranking
        for (int t = tid; t < ng; t += TK_NT) {
            float st = g_agg[(size_t)(start + t) * 4 + c];
            int rank = 0;
            for (int j = 0; j < ng; ++j) {
                float sj = g_agg[(size_t)(start + j) * 4 + c];
                rank += (sj > st) || (sj == st && j < t);
            }
            if (rank < k) atomicOr(&g_mask[start + t], 1 << c);
        }
    }
}

// ---------------------------------------------------------------------------
// Kernel 7: out = x + ((mask*score) @ pools_emb) / (1 + popc(mask))
// warp per node, lane handles 8 features
// ---------------------------------------------------------------------------
__global__ void k_out(const float* __restrict__ x, const float* __restrict__ pe,
                      float* __restrict__ out, int n) {
    __shared__ float4 s_pe[CC * (INCH / 4)];
    int tid = threadIdx.x;
    for (int t = tid; t < CC * (INCH / 4); t += blockDim.x)
        s_pe[t] = ((const float4*)pe)[t];
    __syncthreads();

    int gwarp = (blockIdx.x * blockDim.x + tid) >> 5;
    int lane  = tid & 31;
    if (gwarp >= n) return;

    int   m   = g_mask[gwarp];
    float inv = 1.0f / (1.0f + (float)__popc(m & 0xF));
    float4 s  = ((const float4*)g_agg)[gwarp];
    float w0 = (m & 1) ? s.x * inv : 0.f;
    float w1 = (m & 2) ? s.y * inv : 0.f;
    float w2 = (m & 4) ? s.z * inv : 0.f;
    float w3 = (m & 8) ? s.w * inv : 0.f;

    const float4* xr   = (const float4*)(x + (size_t)gwarp * INCH);
    float4*       orow = (float4*)(out + (size_t)gwarp * INCH);
#pragma unroll
    for (int it = 0; it < 2; ++it) {
        int k4 = lane + it * 32;
        float4 xv = xr[k4];
        float4 p0 = s_pe[0 * 64 + k4];
        float4 p1 = s_pe[1 * 64 + k4];
        float4 p2 = s_pe[2 * 64 + k4];
        float4 p3 = s_pe[3 * 64 + k4];
        float4 o;
        o.x = xv.x + w0 * p0.x + w1 * p1.x + w2 * p2.x + w3 * p3.x;
        o.y = xv.y + w0 * p0.y + w1 * p1.y + w2 * p2.y + w3 * p3.y;
        o.z = xv.z + w0 * p0.z + w1 * p1.z + w2 * p2.z + w3 * p3.z;
        o.w = xv.w + w0 * p0.w + w1 * p1.w + w2 * p2.w + w3 * p3.w;
        orow[k4] = o;
    }
}

// ---------------------------------------------------------------------------
extern "C" void kernel_launch(void* const* d_in, const int* in_sizes, int n_in,
                              void* d_out, int out_size) {
    const float* x     = (const float*)d_in[0];
    const int*   ei    = (const int*)  d_in[1];
    const int*   batch = (const int*)  d_in[2];
    const float* pe    = (const float*)d_in[3];
    const float* W     = (const float*)d_in[4];
    const float* b     = (const float*)d_in[5];
    float*       out   = (float*)d_out;

    int n = in_sizes[0] / INCH;
    int E = in_sizes[1] / 2;
    int quarterE = (E + 3) >> 2;

    int warpBlocks = (n + 7) / 8;               // 8 warps (nodes) per 256-thread block
    k_xw   <<<warpBlocks, 256>>>(x, pe, W, n);
    k_deg  <<<(E + 255) / 256, 256>>>(ei + E, E);
    k_prep <<<(n + 255) / 256, 256>>>(n);
    k_edge <<<(quarterE + 255) / 256, 256>>>(ei, E);
    k_score<<<(n + 255) / 256, 256>>>(b, n);
    k_topk <<<BGRAPH * CC, TK_NT>>>(batch, n);
    k_out  <<<warpBlocks, 256>>>(x, pe, out, n);
}

// round 5
// speedup vs baseline: 1.2996x; 1.0369x over previous
#include <cuda_runtime.h>
#include <stdint.h>

#define NMAX   100000
#define CC     4
#define INCH   256
#define BGRAPH 64
#define SORTN  2048
#define TK_NT  512

// Scratch (device globals; no allocation allowed)
__device__ float g_xw[NMAX * CC];     // (x+pe_sum)@W, then premultiplied by dinv
__device__ float g_agg[NMAX * CC];    // raw edge aggregation -> becomes score
__device__ float g_deg[NMAX];         // degree accumulator (self-resets in k_prep)
__device__ float g_dinv[NMAX];        // rsqrt(degree)
__device__ int   g_mask[NMAX];        // 4-bit selection mask per node

// ---------------------------------------------------------------------------
// Phase A (heterogeneous grid):
//   blocks [0, xwBlocks):        xw = (x + sum_c pe[c]) @ W ; agg=0 ; mask=0
//   blocks [xwBlocks, +degBlk):  g_deg[col[e]] += 1  (4 edges per thread)
// The deg atomics hide under the x stream.
// ---------------------------------------------------------------------------
__global__ void k_phaseA(const float* __restrict__ x, const float* __restrict__ pe,
                         const float* __restrict__ W, const int* __restrict__ col,
                         int n, int E, int xwBlocks) {
    __shared__ float  s_pes[INCH];
    __shared__ float4 s_W[INCH];
    int tid = threadIdx.x;

    if (blockIdx.x >= xwBlocks) {
        // ---- degree role ----
        int b = blockIdx.x - xwBlocks;
        int e = b * 1024 + tid;
#pragma unroll
        for (int it = 0; it < 4; ++it) {
            int ee = e + it * 256;
            if (ee < E) atomicAdd(&g_deg[__ldcs(&col[ee])], 1.0f);
        }
        return;
    }

    // ---- xw role ----
    for (int t = tid; t < INCH; t += blockDim.x) {
        s_pes[t] = pe[t] + pe[INCH + t] + pe[2 * INCH + t] + pe[3 * INCH + t];
        s_W[t]   = ((const float4*)W)[t];
    }
    __syncthreads();

    int gwarp = (blockIdx.x * blockDim.x + tid) >> 5;
    int lane  = tid & 31;
    if (gwarp >= n) return;

    const float4* xr = (const float4*)(x + (size_t)gwarp * INCH);
    float a0 = 0.f, a1 = 0.f, a2 = 0.f, a3 = 0.f;
#pragma unroll
    for (int it = 0; it < 2; ++it) {
        int k4 = lane + it * 32;
        float4 xv = __ldcs(&xr[k4]);
        int k = k4 * 4;
        float x0 = xv.x + s_pes[k + 0];
        float x1 = xv.y + s_pes[k + 1];
        float x2 = xv.z + s_pes[k + 2];
        float x3 = xv.w + s_pes[k + 3];
        float4 w0 = s_W[k + 0], w1 = s_W[k + 1], w2 = s_W[k + 2], w3 = s_W[k + 3];
        a0 += x0 * w0.x + x1 * w1.x + x2 * w2.x + x3 * w3.x;
        a1 += x0 * w0.y + x1 * w1.y + x2 * w2.y + x3 * w3.y;
        a2 += x0 * w0.z + x1 * w1.z + x2 * w2.z + x3 * w3.z;
        a3 += x0 * w0.w + x1 * w1.w + x2 * w2.w + x3 * w3.w;
    }
#pragma unroll
    for (int o = 16; o; o >>= 1) {
        a0 += __shfl_xor_sync(0xffffffffu, a0, o);
        a1 += __shfl_xor_sync(0xffffffffu, a1, o);
        a2 += __shfl_xor_sync(0xffffffffu, a2, o);
        a3 += __shfl_xor_sync(0xffffffffu, a3, o);
    }
    if (lane == 0) {
        ((float4*)g_xw)[gwarp]  = make_float4(a0, a1, a2, a3);
        ((float4*)g_agg)[gwarp] = make_float4(0.f, 0.f, 0.f, 0.f);
        g_mask[gwarp] = 0;
    }
}

// ---------------------------------------------------------------------------
// k_prep: dinv = rsqrt(deg+1 self-loop); reset g_deg for next replay;
//         premultiply xw by dinv (xws = dinv * xw)
// ---------------------------------------------------------------------------
__global__ void k_prep(int n) {
    int i = blockIdx.x * blockDim.x + threadIdx.x;
    if (i >= n) return;
    float d = rsqrtf(g_deg[i] + 1.0f);
    g_deg[i] = 0.0f;                      // self-clean for graph replay
    g_dinv[i] = d;
    float4 v = ((const float4*)g_xw)[i];
    v.x *= d; v.y *= d; v.z *= d; v.w *= d;
    ((float4*)g_xw)[i] = v;
}

// ---------------------------------------------------------------------------
// k_edge: agg[col] += xws[row]   (dinv[col] applied at score time)
// 4 edges per thread, loads front-batched for MLP against L2 latency
// ---------------------------------------------------------------------------
__global__ void k_edge(const int* __restrict__ ei, int E) {
    int t = blockIdx.x * blockDim.x + threadIdx.x;
    int quarter = (E + 3) >> 2;
    int e0 = t;
    if (e0 >= quarter) return;
    int e1 = e0 + quarter, e2 = e0 + 2 * quarter, e3 = e0 + 3 * quarter;
    bool h1 = e1 < E, h2 = e2 < E, h3 = e3 < E;

    int r0 = __ldcs(&ei[e0]);
    int r1 = h1 ? __ldcs(&ei[e1]) : r0;
    int r2 = h2 ? __ldcs(&ei[e2]) : r0;
    int r3 = h3 ? __ldcs(&ei[e3]) : r0;
    int c0 = __ldcs(&ei[E + e0]);
    int c1 = h1 ? __ldcs(&ei[E + e1]) : c0;
    int c2 = h2 ? __ldcs(&ei[E + e2]) : c0;
    int c3 = h3 ? __ldcs(&ei[E + e3]) : c0;

    float4 v0 = ((const float4*)g_xw)[r0];
    float4 v1 = ((const float4*)g_xw)[r1];
    float4 v2 = ((const float4*)g_xw)[r2];
    float4 v3 = ((const float4*)g_xw)[r3];

    asm volatile("red.global.add.v4.f32 [%0], {%1, %2, %3, %4};"
                 :: "l"(&g_agg[4 * c0]), "f"(v0.x), "f"(v0.y), "f"(v0.z), "f"(v0.w)
                 : "memory");
    if (h1)
        asm volatile("red.global.add.v4.f32 [%0], {%1, %2, %3, %4};"
                     :: "l"(&g_agg[4 * c1]), "f"(v1.x), "f"(v1.y), "f"(v1.z), "f"(v1.w)
                     : "memory");
    if (h2)
        asm volatile("red.global.add.v4.f32 [%0], {%1, %2, %3, %4};"
                     :: "l"(&g_agg[4 * c2]), "f"(v2.x), "f"(v2.y), "f"(v2.z), "f"(v2.w)
                     : "memory");
    if (h3)
        asm volatile("red.global.add.v4.f32 [%0], {%1, %2, %3, %4};"
                     :: "l"(&g_agg[4 * c3]), "f"(v3.x), "f"(v3.y), "f"(v3.z), "f"(v3.w)
                     : "memory");
}

// ---------------------------------------------------------------------------
// Block-wide exclusive scan over TK_NT ints (one per thread).
// ---------------------------------------------------------------------------
__device__ __forceinline__ int block_excl_scan(int v, int tid, int* s_wsum) {
    const int NW = TK_NT / 32;
    int lane = tid & 31, wid = tid >> 5;
    int orig = v;
#pragma unroll
    for (int o = 1; o < 32; o <<= 1) {
        int t = __shfl_up_sync(0xffffffffu, v, o);
        if (lane >= o) v += t;
    }
    if (lane == 31) s_wsum[wid] = v;
    __syncthreads();
    if (wid == 0 && lane < NW) {
        int w = s_wsum[lane];
#pragma unroll
        for (int o = 1; o < NW; o <<= 1) {
            int t = __shfl_up_sync((1u << NW) - 1u, w, o, NW);
            if (lane >= o) w += t;
        }
        s_wsum[lane] = w;
    }
    __syncthreads();
    return v + (wid ? s_wsum[wid - 1] : 0) - orig;
}

// ---------------------------------------------------------------------------
// k_topk: per (graph, column). Computes score = tanh(dinv*(agg+xws)+b[c])
// (stores it back to g_agg for k_out), then MSB radix select (4 byte passes)
// over u = ~orderable(score); ties by smallest index == jax stable lexsort.
// ---------------------------------------------------------------------------
__global__ void k_topk(const int* __restrict__ batch, const float* __restrict__ bb,
                       int n) {
    __shared__ unsigned s_u[SORTN];
    __shared__ int s_hist[256];
    __shared__ int s_wsum[TK_NT / 32];
    __shared__ int s_bounds[2];
    __shared__ unsigned s_prefix;
    __shared__ int s_target;

    int g = blockIdx.x >> 2;
    int c = blockIdx.x & 3;
    int tid = threadIdx.x;

    if (tid == 0) {
        int lo = 0, hi = n;
        while (lo < hi) { int m = (lo + hi) >> 1; if (batch[m] < g) lo = m + 1; else hi = m; }
        s_bounds[0] = lo;
        hi = n;
        while (lo < hi) { int m = (lo + hi) >> 1; if (batch[m] < g + 1) lo = m + 1; else hi = m; }
        s_bounds[1] = lo;
        s_prefix = 0u;
    }
    __syncthreads();
    int start = s_bounds[0];
    int ng    = s_bounds[1] - s_bounds[0];
    int k     = (ng + 1) >> 1;            // ceil(0.5 * ng)
    if (k == 0) return;
    float bc = bb[c];

    // compute scores for this slice, store back, build selection keys
    for (int t = tid; t < ng; t += TK_NT) {
        size_t idx = (size_t)(start + t) * 4 + c;
        float d = g_dinv[start + t];
        float s = tanhf(d * (g_agg[idx] + g_xw[idx]) + bc);
        g_agg[idx] = s;                   // k_out reads this
        if (t < SORTN) {
            unsigned u = __float_as_uint(s);
            u = (u & 0x80000000u) ? ~u : (u | 0x80000000u);  // ascending float order
            s_u[t] = ~u;                                      // descending score
        }
    }
    if (tid == 0) s_target = k - 1;       // 0-based rank of threshold key
    __syncthreads();

    if (ng <= SORTN) {
        unsigned done_mask = 0u;
#pragma unroll
        for (int pass = 0; pass < 4; ++pass) {
            int shift = 24 - 8 * pass;
            if (tid < 256) s_hist[tid] = 0;
            __syncthreads();
            unsigned pref = s_prefix;
            int tgt = s_target;
            for (int t = tid; t < ng; t += TK_NT) {
                unsigned u = s_u[t];
                if ((u & done_mask) == pref)
                    atomicAdd(&s_hist[(u >> shift) & 255u], 1);
            }
            __syncthreads();
            int h    = (tid < 256) ? s_hist[tid] : 0;
            int excl = block_excl_scan(h, tid, s_wsum);
            if (tid < 256 && excl <= tgt && tgt < excl + h) {
                s_prefix |= ((unsigned)tid) << shift;
                s_target = tgt - excl;
            }
            done_mask |= 0xFFu << shift;
            __syncthreads();
        }
        unsigned T = s_prefix;            // threshold key
        int r = s_target;                 // rank among equals still selected

        // stable tie ranking: chunked exclusive count of (u == T)
        int chunk = (ng + TK_NT - 1) / TK_NT;
        int lo = min(tid * chunk, ng);
        int hi = min(lo + chunk, ng);
        int cnt = 0;
        for (int t = lo; t < hi; ++t) cnt += (s_u[t] == T);
        int eqrank = block_excl_scan(cnt, tid, s_wsum);
        for (int t = lo; t < hi; ++t) {
            unsigned u = s_u[t];
            bool sel = (u < T) || (u == T && eqrank <= r);
            eqrank += (u == T);
            if (sel) atomicOr(&g_mask[start + t], 1 << c);
        }
    } else {
        // Fallback (never expected at these sizes): O(n^2) exact ranking
        for (int t = tid; t < ng; t += TK_NT) {
            float st = g_agg[(size_t)(start + t) * 4 + c];
            int rank = 0;
            for (int j = 0; j < ng; ++j) {
                float sj = g_agg[(size_t)(start + j) * 4 + c];
                rank += (sj > st) || (sj == st && j < t);
            }
            if (rank < k) atomicOr(&g_mask[start + t], 1 << c);
        }
    }
}

// ---------------------------------------------------------------------------
// k_out: out = x + ((mask*score) @ pools_emb) / (1 + popc(mask))
// warp per node, lane handles 8 features
// ---------------------------------------------------------------------------
__global__ void k_out(const float* __restrict__ x, const float* __restrict__ pe,
                      float* __restrict__ out, int n) {
    __shared__ float4 s_pe[CC * (INCH / 4)];
    int tid = threadIdx.x;
    for (int t = tid; t < CC * (INCH / 4); t += blockDim.x)
        s_pe[t] = ((const float4*)pe)[t];
    __syncthreads();

    int gwarp = (blockIdx.x * blockDim.x + tid) >> 5;
    int lane  = tid & 31;
    if (gwarp >= n) return;

    int   m   = g_mask[gwarp];
    float inv = 1.0f / (1.0f + (float)__popc(m & 0xF));
    float4 s  = ((const float4*)g_agg)[gwarp];
    float w0 = (m & 1) ? s.x * inv : 0.f;
    float w1 = (m & 2) ? s.y * inv : 0.f;
    float w2 = (m & 4) ? s.z * inv : 0.f;
    float w3 = (m & 8) ? s.w * inv : 0.f;

    const float4* xr   = (const float4*)(x + (size_t)gwarp * INCH);
    float4*       orow = (float4*)(out + (size_t)gwarp * INCH);
#pragma unroll
    for (int it = 0; it < 2; ++it) {
        int k4 = lane + it * 32;
        float4 xv = __ldcs(&xr[k4]);
        float4 p0 = s_pe[0 * 64 + k4];
        float4 p1 = s_pe[1 * 64 + k4];
        float4 p2 = s_pe[2 * 64 + k4];
        float4 p3 = s_pe[3 * 64 + k4];
        float4 o;
        o.x = xv.x + w0 * p0.x + w1 * p1.x + w2 * p2.x + w3 * p3.x;
        o.y = xv.y + w0 * p0.y + w1 * p1.y + w2 * p2.y + w3 * p3.y;
        o.z = xv.z + w0 * p0.z + w1 * p1.z + w2 * p2.z + w3 * p3.z;
        o.w = xv.w + w0 * p0.w + w1 * p1.w + w2 * p2.w + w3 * p3.w;
        __stcs(&orow[k4], o);
    }
}

// ---------------------------------------------------------------------------
extern "C" void kernel_launch(void* const* d_in, const int* in_sizes, int n_in,
                              void* d_out, int out_size) {
    const float* x     = (const float*)d_in[0];
    const int*   ei    = (const int*)  d_in[1];
    const int*   batch = (const int*)  d_in[2];
    const float* pe    = (const float*)d_in[3];
    const float* W     = (const float*)d_in[4];
    const float* b     = (const float*)d_in[5];
    float*       out   = (float*)d_out;

    int n = in_sizes[0] / INCH;
    int E = in_sizes[1] / 2;
    int quarterE  = (E + 3) >> 2;
    int xwBlocks  = (n + 7) / 8;
    int degBlocks = (E + 1023) / 1024;

    k_phaseA<<<xwBlocks + degBlocks, 256>>>(x, pe, W, ei + E, n, E, xwBlocks);
    k_prep  <<<(n + 255) / 256, 256>>>(n);
    k_edge  <<<(quarterE + 255) / 256, 256>>>(ei, E);
    k_topk  <<<BGRAPH * CC, TK_NT>>>(batch, b, n);
    k_out   <<<xwBlocks, 256>>>(x, pe, out, n);
}

// round 7
// speedup vs baseline: 1.3300x; 1.0234x over previous
#include <cuda_runtime.h>
#include <stdint.h>

#define NMAX   100000
#define CC     4
#define INCH   256
#define BGRAPH 64
#define SORTN  2048
#define TK_NT  512

// Scratch (device globals; no allocation allowed)
__device__ float g_xw[NMAX * CC];     // (x+pe_sum)@W, then premultiplied by dinv
__device__ float g_agg[NMAX * CC];    // raw edge aggregation -> becomes score
__device__ float g_deg[NMAX];         // degree accumulator (self-resets in k_prep)
__device__ float g_dinv[NMAX];        // rsqrt(degree)
__device__ int   g_mask[NMAX];        // 4-bit selection mask per node

// ---------------------------------------------------------------------------
// Phase A (heterogeneous grid):
//   blocks [0, xwBlocks):        xw = (x + sum_c pe[c]) @ W ; agg=0 ; mask=0
//   blocks [xwBlocks, +degBlk):  g_deg[col[e]] += 1
// ---------------------------------------------------------------------------
__global__ void k_phaseA(const float* __restrict__ x, const float* __restrict__ pe,
                         const float* __restrict__ W, const int* __restrict__ col,
                         int n, int E, int xwBlocks) {
    __shared__ float  s_pes[INCH];
    __shared__ float4 s_W[INCH];
    int tid = threadIdx.x;

    if (blockIdx.x >= xwBlocks) {
        int b = blockIdx.x - xwBlocks;
        int e = b * 1024 + tid;
#pragma unroll
        for (int it = 0; it < 4; ++it) {
            int ee = e + it * 256;
            if (ee < E) atomicAdd(&g_deg[__ldcs(&col[ee])], 1.0f);
        }
        return;
    }

    for (int t = tid; t < INCH; t += blockDim.x) {
        s_pes[t] = pe[t] + pe[INCH + t] + pe[2 * INCH + t] + pe[3 * INCH + t];
        s_W[t]   = ((const float4*)W)[t];
    }
    __syncthreads();

    int gwarp = (blockIdx.x * blockDim.x + tid) >> 5;
    int lane  = tid & 31;
    if (gwarp >= n) return;

    const float4* xr = (const float4*)(x + (size_t)gwarp * INCH);
    float a0 = 0.f, a1 = 0.f, a2 = 0.f, a3 = 0.f;
#pragma unroll
    for (int it = 0; it < 2; ++it) {
        int k4 = lane + it * 32;
        float4 xv = __ldcs(&xr[k4]);
        int k = k4 * 4;
        float x0 = xv.x + s_pes[k + 0];
        float x1 = xv.y + s_pes[k + 1];
        float x2 = xv.z + s_pes[k + 2];
        float x3 = xv.w + s_pes[k + 3];
        float4 w0 = s_W[k + 0], w1 = s_W[k + 1], w2 = s_W[k + 2], w3 = s_W[k + 3];
        a0 += x0 * w0.x + x1 * w1.x + x2 * w2.x + x3 * w3.x;
        a1 += x0 * w0.y + x1 * w1.y + x2 * w2.y + x3 * w3.y;
        a2 += x0 * w0.z + x1 * w1.z + x2 * w2.z + x3 * w3.z;
        a3 += x0 * w0.w + x1 * w1.w + x2 * w2.w + x3 * w3.w;
    }
#pragma unroll
    for (int o = 16; o; o >>= 1) {
        a0 += __shfl_xor_sync(0xffffffffu, a0, o);
        a1 += __shfl_xor_sync(0xffffffffu, a1, o);
        a2 += __shfl_xor_sync(0xffffffffu, a2, o);
        a3 += __shfl_xor_sync(0xffffffffu, a3, o);
    }
    if (lane == 0) {
        ((float4*)g_xw)[gwarp]  = make_float4(a0, a1, a2, a3);
        ((float4*)g_agg)[gwarp] = make_float4(0.f, 0.f, 0.f, 0.f);
        g_mask[gwarp] = 0;
    }
}

// ---------------------------------------------------------------------------
// k_prep: dinv = rsqrt(deg+1); reset g_deg; premultiply xw by dinv
// ---------------------------------------------------------------------------
__global__ void k_prep(int n) {
    int i = blockIdx.x * blockDim.x + threadIdx.x;
    if (i >= n) return;
    float d = rsqrtf(g_deg[i] + 1.0f);
    g_deg[i] = 0.0f;
    g_dinv[i] = d;
    float4 v = ((const float4*)g_xw)[i];
    v.x *= d; v.y *= d; v.z *= d; v.w *= d;
    ((float4*)g_xw)[i] = v;
}

// ---------------------------------------------------------------------------
// k_edge: agg[col] += xws[row]. 8 consecutive edges per thread; int4 index
// loads; gathers front-batched for MLP=8 against L2 latency.
// ---------------------------------------------------------------------------
__global__ void k_edge(const int* __restrict__ ei, int E) {
    int t = blockIdx.x * blockDim.x + threadIdx.x;
    int base = t * 8;
    if (base >= E) return;

    if (base + 8 <= E) {
        int4 ra = __ldcs((const int4*)(ei + base));
        int4 rb = __ldcs((const int4*)(ei + base + 4));
        int4 ca = __ldcs((const int4*)(ei + E + base));
        int4 cb = __ldcs((const int4*)(ei + E + base + 4));

        float4 v0 = ((const float4*)g_xw)[ra.x];
        float4 v1 = ((const float4*)g_xw)[ra.y];
        float4 v2 = ((const float4*)g_xw)[ra.z];
        float4 v3 = ((const float4*)g_xw)[ra.w];
        float4 v4 = ((const float4*)g_xw)[rb.x];
        float4 v5 = ((const float4*)g_xw)[rb.y];
        float4 v6 = ((const float4*)g_xw)[rb.z];
        float4 v7 = ((const float4*)g_xw)[rb.w];

#define RED4(cidx, v) \
        asm volatile("red.global.add.v4.f32 [%0], {%1, %2, %3, %4};" \
                     :: "l"(&g_agg[4 * (cidx)]), "f"((v).x), "f"((v).y), "f"((v).z), "f"((v).w) \
                     : "memory")
        RED4(ca.x, v0); RED4(ca.y, v1); RED4(ca.z, v2); RED4(ca.w, v3);
        RED4(cb.x, v4); RED4(cb.y, v5); RED4(cb.z, v6); RED4(cb.w, v7);
    } else {
        for (int e = base; e < E; ++e) {
            int r = ei[e], c = ei[E + e];
            float4 v = ((const float4*)g_xw)[r];
            RED4(c, v);
        }
    }
#undef RED4
}

// ---------------------------------------------------------------------------
// Block-wide exclusive scan over TK_NT ints (one per thread).
// ---------------------------------------------------------------------------
__device__ __forceinline__ int block_excl_scan(int v, int tid, int* s_wsum) {
    const int NW = TK_NT / 32;
    int lane = tid & 31, wid = tid >> 5;
    int orig = v;
#pragma unroll
    for (int o = 1; o < 32; o <<= 1) {
        int t = __shfl_up_sync(0xffffffffu, v, o);
        if (lane >= o) v += t;
    }
    if (lane == 31) s_wsum[wid] = v;
    __syncthreads();
    if (wid == 0 && lane < NW) {
        int w = s_wsum[lane];
#pragma unroll
        for (int o = 1; o < NW; o <<= 1) {
            int t = __shfl_up_sync((1u << NW) - 1u, w, o, NW);
            if (lane >= o) w += t;
        }
        s_wsum[lane] = w;
    }
    __syncthreads();
    return v + (wid ? s_wsum[wid - 1] : 0) - orig;
}

// ---------------------------------------------------------------------------
// k_topk: per (graph, column). Cooperative p-ary bounds search, fused score
// compute (tanh), MSB radix select with stable tie ranking.
// ---------------------------------------------------------------------------
__global__ void k_topk(const int* __restrict__ batch, const float* __restrict__ bb,
                       int n) {
    __shared__ unsigned s_u[SORTN];
    __shared__ int s_hist[256];
    __shared__ int s_wsum[TK_NT / 32];
    __shared__ int s_p0, s_p1;            // probe mins / position mins
    __shared__ unsigned s_prefix;
    __shared__ int s_target;

    int g = blockIdx.x >> 2;
    int c = blockIdx.x & 3;
    int tid = threadIdx.x;

    // ---- cooperative two-phase search for [start, end) of graph g ----
    if (tid == 0) { s_p0 = TK_NT; s_p1 = TK_NT; s_prefix = 0u; }
    __syncthreads();
    int stride = (n + TK_NT - 1) / TK_NT;
    {
        int pos = tid * stride;
        int v = (pos < n) ? batch[pos] : 0x7fffffff;
        if (v >= g)     atomicMin(&s_p0, tid);
        if (v >= g + 1) atomicMin(&s_p1, tid);
    }
    __syncthreads();
    int t0 = s_p0, t1 = s_p1;
    __syncthreads();
    if (tid == 0) { s_p0 = n; s_p1 = n; }
    __syncthreads();
    {
        // bracket for bound: ((t-1)*stride, t*stride]; t==0 -> [0..0]
        int half = tid & 255;
        if (tid < 256) {
            int lo = (t0 == 0) ? 0 : (t0 - 1) * stride + 1;
            int hi = min(t0 * stride, n - 1);
            int idx = lo + half;
            if (idx <= hi && batch[idx] >= g) atomicMin(&s_p0, idx);
        } else {
            int lo = (t1 == 0) ? 0 : (t1 - 1) * stride + 1;
            int hi = min(t1 * stride, n - 1);
            int idx = lo + half;
            if (idx <= hi && batch[idx] >= g + 1) atomicMin(&s_p1, idx);
        }
    }
    __syncthreads();
    int start = s_p0;
    int ng    = s_p1 - s_p0;
    int k     = (ng + 1) >> 1;            // ceil(0.5 * ng)
    if (k <= 0) return;
    float bc = bb[c];

    // ---- fused score compute + key build ----
    for (int t = tid; t < ng; t += TK_NT) {
        size_t idx = (size_t)(start + t) * 4 + c;
        float d = g_dinv[start + t];
        float s = tanhf(d * (g_agg[idx] + g_xw[idx]) + bc);
        g_agg[idx] = s;                   // k_out reads this
        if (t < SORTN) {
            unsigned u = __float_as_uint(s);
            u = (u & 0x80000000u) ? ~u : (u | 0x80000000u);  // ascending float order
            s_u[t] = ~u;                                      // descending score
        }
    }
    if (tid == 0) s_target = k - 1;
    __syncthreads();

    if (ng <= SORTN) {
        unsigned done_mask = 0u;
#pragma unroll
        for (int pass = 0; pass < 4; ++pass) {
            int shift = 24 - 8 * pass;
            if (tid < 256) s_hist[tid] = 0;
            __syncthreads();
            unsigned pref = s_prefix;
            int tgt = s_target;
            for (int t = tid; t < ng; t += TK_NT) {
                unsigned u = s_u[t];
                if ((u & done_mask) == pref)
                    atomicAdd(&s_hist[(u >> shift) & 255u], 1);
            }
            __syncthreads();
            int h    = (tid < 256) ? s_hist[tid] : 0;
            int excl = block_excl_scan(h, tid, s_wsum);
            if (tid < 256 && excl <= tgt && tgt < excl + h) {
                s_prefix |= ((unsigned)tid) << shift;
                s_target = tgt - excl;
            }
            done_mask |= 0xFFu << shift;
            __syncthreads();
        }
        unsigned T = s_prefix;
        int r = s_target;

        // stable tie ranking: chunked exclusive count of (u == T)
        int chunk = (ng + TK_NT - 1) / TK_NT;
        int lo = min(tid * chunk, ng);
        int hi = min(lo + chunk, ng);
        int cnt = 0;
        for (int t = lo; t < hi; ++t) cnt += (s_u[t] == T);
        int eqrank = block_excl_scan(cnt, tid, s_wsum);
        for (int t = lo; t < hi; ++t) {
            unsigned u = s_u[t];
            bool sel = (u < T) || (u == T && eqrank <= r);
            eqrank += (u == T);
            if (sel) atomicOr(&g_mask[start + t], 1 << c);
        }
    } else {
        // Fallback (never expected): O(n^2) exact ranking
        for (int t = tid; t < ng; t += TK_NT) {
            float st = g_agg[(size_t)(start + t) * 4 + c];
            int rank = 0;
            for (int j = 0; j < ng; ++j) {
                float sj = g_agg[(size_t)(start + j) * 4 + c];
                rank += (sj > st) || (sj == st && j < t);
            }
            if (rank < k) atomicOr(&g_mask[start + t], 1 << c);
        }
    }
}

// ---------------------------------------------------------------------------
// k_out: out = x + ((mask*score) @ pools_emb) / (1 + popc(mask))
// ---------------------------------------------------------------------------
__global__ void k_out(const float* __restrict__ x, const float* __restrict__ pe,
                      float* __restrict__ out, int n) {
    __shared__ float4 s_pe[CC * (INCH / 4)];
    int tid = threadIdx.x;
    for (int t = tid; t < CC * (INCH / 4); t += blockDim.x)
        s_pe[t] = ((const float4*)pe)[t];
    __syncthreads();

    int gwarp = (blockIdx.x * blockDim.x + tid) >> 5;
    int lane  = tid & 31;
    if (gwarp >= n) return;

    int   m   = g_mask[gwarp];
    float inv = 1.0f / (1.0f + (float)__popc(m & 0xF));
    float4 s  = ((const float4*)g_agg)[gwarp];
    float w0 = (m & 1) ? s.x * inv : 0.f;
    float w1 = (m & 2) ? s.y * inv : 0.f;
    float w2 = (m & 4) ? s.z * inv : 0.f;
    float w3 = (m & 8) ? s.w * inv : 0.f;

    const float4* xr   = (const float4*)(x + (size_t)gwarp * INCH);
    float4*       orow = (float4*)(out + (size_t)gwarp * INCH);
#pragma unroll
    for (int it = 0; it < 2; ++it) {
        int k4 = lane + it * 32;
        float4 xv = __ldcs(&xr[k4]);
        float4 p0 = s_pe[0 * 64 + k4];
        float4 p1 = s_pe[1 * 64 + k4];
        float4 p2 = s_pe[2 * 64 + k4];
        float4 p3 = s_pe[3 * 64 + k4];
        float4 o;
        o.x = xv.x + w0 * p0.x + w1 * p1.x + w2 * p2.x + w3 * p3.x;
        o.y = xv.y + w0 * p0.y + w1 * p1.y + w2 * p2.y + w3 * p3.y;
        o.z = xv.z + w0 * p0.z + w1 * p1.z + w2 * p2.z + w3 * p3.z;
        o.w = xv.w + w0 * p0.w + w1 * p1.w + w2 * p2.w + w3 * p3.w;
        __stcs(&orow[k4], o);
    }
}

// ---------------------------------------------------------------------------
extern "C" void kernel_launch(void* const* d_in, const int* in_sizes, int n_in,
                              void* d_out, int out_size) {
    const float* x     = (const float*)d_in[0];
    const int*   ei    = (const int*)  d_in[1];
    const int*   batch = (const int*)  d_in[2];
    const float* pe    = (const float*)d_in[3];
    const float* W     = (const float*)d_in[4];
    const float* b     = (const float*)d_in[5];
    float*       out   = (float*)d_out;

    int n = in_sizes[0] / INCH;
    int E = in_sizes[1] / 2;
    int eThreads  = (E + 7) / 8;
    int xwBlocks  = (n + 7) / 8;
    int degBlocks = (E + 1023) / 1024;

    k_phaseA<<<xwBlocks + degBlocks, 256>>>(x, pe, W, ei + E, n, E, xwBlocks);
    k_prep  <<<(n + 255) / 256, 256>>>(n);
    k_edge  <<<(eThreads + 255) / 256, 256>>>(ei, E);
    k_topk  <<<BGRAPH * CC, TK_NT>>>(batch, b, n);
    k_out   <<<xwBlocks, 256>>>(x, pe, out, n);
}

// round 8
// speedup vs baseline: 1.6176x; 1.2162x over previous
#include <cuda_runtime.h>
#include <stdint.h>

#define CC     4
#define INCH   256
#define NT     256
#define SORTN  2048
#define NMAXN  100000
#define NJOBS  256                       // 64 graphs * 4 columns

// Scratch (device globals; no allocation allowed)
__device__ float g_xw[NMAXN * CC];
__device__ float g_agg[NMAXN * CC];
__device__ float g_deg[NMAXN];
__device__ float g_dinv[NMAXN];
__device__ int   g_mask[NMAXN];
__device__ unsigned g_bar_cnt;
__device__ volatile unsigned g_bar_gen;

struct TkS  { unsigned u[SORTN]; int hist[256]; int wsum[8]; };
struct XwS  { float pes[INCH]; float4 Wm[INCH]; };
struct OutS { float4 pe[CC * (INCH / 4)]; };
union SmemU { TkS tk; XwS xw; OutS o; };

__device__ __forceinline__ void gbar() {
    __threadfence();
    __syncthreads();
    if (threadIdx.x == 0) {
        unsigned gen = g_bar_gen;
        if (atomicAdd(&g_bar_cnt, 1u) == gridDim.x - 1u) {
            g_bar_cnt = 0u;
            __threadfence();
            g_bar_gen = gen + 1u;
        } else {
            while (g_bar_gen == gen) __nanosleep(32);
        }
    }
    __syncthreads();
}

__device__ __forceinline__ int scan256(int v, int tid, int* wsum) {
    int lane = tid & 31, wid = tid >> 5, orig = v;
#pragma unroll
    for (int o = 1; o < 32; o <<= 1) {
        int t = __shfl_up_sync(0xffffffffu, v, o);
        if (lane >= o) v += t;
    }
    if (lane == 31) wsum[wid] = v;
    __syncthreads();
    if (wid == 0 && lane < 8) {
        int w = wsum[lane];
#pragma unroll
        for (int o = 1; o < 8; o <<= 1) {
            int t = __shfl_up_sync(0xffu, w, o, 8);
            if (lane >= o) w += t;
        }
        wsum[lane] = w;
    }
    __syncthreads();
    return v + (wid ? wsum[wid - 1] : 0) - orig;
}

__global__ void __launch_bounds__(NT, 3) k_fused(
    const float* __restrict__ x, const int* __restrict__ ei,
    const int* __restrict__ batch, const float* __restrict__ pe,
    const float* __restrict__ W, const float* __restrict__ bb,
    float* __restrict__ out, int n, int E) {
    __shared__ SmemU sm;
    __shared__ int s_p0, s_p1, s_target;
    __shared__ unsigned s_prefix;

    int tid  = threadIdx.x;
    int bid  = blockIdx.x;
    int NB   = gridDim.x;
    int warp = tid >> 5, lane = tid & 31;
    const int* col = ei + E;

    // ===== Phase 1: xw GEMV (4 nodes/warp) + degree atomics, block-stride ===
    for (int t = tid; t < INCH; t += NT) {
        sm.xw.pes[t] = pe[t] + pe[INCH + t] + pe[2 * INCH + t] + pe[3 * INCH + t];
        sm.xw.Wm[t]  = ((const float4*)W)[t];
    }
    __syncthreads();

    int xwU  = (n + 31) >> 5;
    int degU = (E + 1023) >> 10;
    for (int v = bid; v < xwU + degU; v += NB) {
        if (v < xwU) {
            int base = v * 32 + warp * 4;
            float4 xv[4][2];
#pragma unroll
            for (int j = 0; j < 4; ++j) {
                int node = (base + j < n) ? base + j : (n - 1);
                const float4* xr = (const float4*)(x + (size_t)node * INCH);
                xv[j][0] = __ldcs(&xr[lane]);
                xv[j][1] = __ldcs(&xr[lane + 32]);
            }
#pragma unroll
            for (int j = 0; j < 4; ++j) {
                float a0 = 0.f, a1 = 0.f, a2 = 0.f, a3 = 0.f;
#pragma unroll
                for (int it = 0; it < 2; ++it) {
                    int k4 = lane + it * 32;
                    float4 q = xv[j][it];
                    int k = k4 * 4;
                    float x0 = q.x + sm.xw.pes[k + 0];
                    float x1 = q.y + sm.xw.pes[k + 1];
                    float x2 = q.z + sm.xw.pes[k + 2];
                    float x3 = q.w + sm.xw.pes[k + 3];
                    float4 w0 = sm.xw.Wm[k + 0], w1 = sm.xw.Wm[k + 1];
                    float4 w2 = sm.xw.Wm[k + 2], w3 = sm.xw.Wm[k + 3];
                    a0 += x0 * w0.x + x1 * w1.x + x2 * w2.x + x3 * w3.x;
                    a1 += x0 * w0.y + x1 * w1.y + x2 * w2.y + x3 * w3.y;
                    a2 += x0 * w0.z + x1 * w1.z + x2 * w2.z + x3 * w3.z;
                    a3 += x0 * w0.w + x1 * w1.w + x2 * w2.w + x3 * w3.w;
                }
#pragma unroll
                for (int o = 16; o; o >>= 1) {
                    a0 += __shfl_xor_sync(0xffffffffu, a0, o);
                    a1 += __shfl_xor_sync(0xffffffffu, a1, o);
                    a2 += __shfl_xor_sync(0xffffffffu, a2, o);
                    a3 += __shfl_xor_sync(0xffffffffu, a3, o);
                }
                if (lane == 0 && base + j < n) {
                    ((float4*)g_xw)[base + j]  = make_float4(a0, a1, a2, a3);
                    ((float4*)g_agg)[base + j] = make_float4(0.f, 0.f, 0.f, 0.f);
                    g_mask[base + j] = 0;
                }
            }
        } else {
            int d = v - xwU;
            int e = d * 1024 + tid;
#pragma unroll
            for (int it = 0; it < 4; ++it) {
                int ee = e + it * 256;
                if (ee < E) atomicAdd(&g_deg[__ldcs(&col[ee])], 1.0f);
            }
        }
    }
    gbar();

    // ===== Phase 2: prep ====================================================
    for (int i = bid * NT + tid; i < n; i += NB * NT) {
        float d = rsqrtf(g_deg[i] + 1.0f);
        g_deg[i]  = 0.0f;
        g_dinv[i] = d;
        float4 v = ((const float4*)g_xw)[i];
        v.x *= d; v.y *= d; v.z *= d; v.w *= d;
        ((float4*)g_xw)[i] = v;
    }
    gbar();

    // ===== Phase 3: edge aggregation ========================================
    {
        int eU = (E + 7) >> 3;
        for (int t = bid * NT + tid; t < eU; t += NB * NT) {
            int base = t * 8;
            if (base + 8 <= E) {
                int4 ra = __ldcs((const int4*)(ei + base));
                int4 rb = __ldcs((const int4*)(ei + base + 4));
                int4 ca = __ldcs((const int4*)(col + base));
                int4 cb = __ldcs((const int4*)(col + base + 4));
                float4 v0 = ((const float4*)g_xw)[ra.x];
                float4 v1 = ((const float4*)g_xw)[ra.y];
                float4 v2 = ((const float4*)g_xw)[ra.z];
                float4 v3 = ((const float4*)g_xw)[ra.w];
                float4 v4 = ((const float4*)g_xw)[rb.x];
                float4 v5 = ((const float4*)g_xw)[rb.y];
                float4 v6 = ((const float4*)g_xw)[rb.z];
                float4 v7 = ((const float4*)g_xw)[rb.w];
#define RED4(cidx, v) \
                asm volatile("red.global.add.v4.f32 [%0], {%1, %2, %3, %4};" \
                             :: "l"(&g_agg[4 * (cidx)]), "f"((v).x), "f"((v).y), "f"((v).z), "f"((v).w) \
                             : "memory")
                RED4(ca.x, v0); RED4(ca.y, v1); RED4(ca.z, v2); RED4(ca.w, v3);
                RED4(cb.x, v4); RED4(cb.y, v5); RED4(cb.z, v6); RED4(cb.w, v7);
            } else {
                for (int e = base; e < E; ++e) {
                    int r = ei[e], c = col[e];
                    float4 v = ((const float4*)g_xw)[r];
                    RED4(c, v);
                }
            }
#undef RED4
        }
    }
    gbar();

    // ===== Phase 4: score + top-k per (graph, column) =======================
    for (int job = bid; job < NJOBS; job += NB) {
        int g = job >> 2;
        int c = job & 3;

        if (tid == 0) { s_p0 = NT; s_p1 = NT; s_prefix = 0u; }
        __syncthreads();
        int stride = (n + NT - 1) / NT;
        {
            int pos = tid * stride;
            int v = (pos < n) ? batch[pos] : 0x7fffffff;
            if (v >= g)     atomicMin(&s_p0, tid);
            if (v >= g + 1) atomicMin(&s_p1, tid);
        }
        __syncthreads();
        int t0 = s_p0, t1 = s_p1;
        __syncthreads();
        if (tid == 0) { s_p0 = n; s_p1 = n; }
        __syncthreads();
        {
            int lo0 = (t0 == 0) ? 0 : (t0 - 1) * stride + 1;
            int hi0 = min(t0 * stride, n - 1);
            for (int idx = lo0 + tid; idx <= hi0; idx += NT)
                if (batch[idx] >= g) atomicMin(&s_p0, idx);
            int lo1 = (t1 == 0) ? 0 : (t1 - 1) * stride + 1;
            int hi1 = min(t1 * stride, n - 1);
            for (int idx = lo1 + tid; idx <= hi1; idx += NT)
                if (batch[idx] >= g + 1) atomicMin(&s_p1, idx);
        }
        __syncthreads();
        int start = s_p0;
        int ng    = s_p1 - s_p0;
        if (ng < 0) ng = 0;
        int k     = (ng + 1) >> 1;
        float bc  = bb[c];

        for (int t = tid; t < ng; t += NT) {
            size_t idx = (size_t)(start + t) * 4 + c;
            float d = g_dinv[start + t];
            float s = tanhf(d * (__ldcg(&g_agg[idx]) + g_xw[idx]) + bc);
            __stcg(&g_agg[idx], s);
            if (t < SORTN) {
                unsigned u = __float_as_uint(s);
                u = (u & 0x80000000u) ? ~u : (u | 0x80000000u);
                sm.tk.u[t] = ~u;
            }
        }
        if (tid == 0) s_target = k - 1;
        __syncthreads();

        if (ng <= SORTN) {
            unsigned done_mask = 0u;
#pragma unroll
            for (int pass = 0; pass < 4; ++pass) {
                int shift = 24 - 8 * pass;
                sm.tk.hist[tid] = 0;
                __syncthreads();
                unsigned pref = s_prefix;
                int tgt = s_target;
                for (int t = tid; t < ng; t += NT) {
                    unsigned u = sm.tk.u[t];
                    if ((u & done_mask) == pref)
                        atomicAdd(&sm.tk.hist[(u >> shift) & 255u], 1);
                }
                __syncthreads();
                int h    = sm.tk.hist[tid];
                int excl = scan256(h, tid, sm.tk.wsum);
                if (excl <= tgt && tgt < excl + h) {
                    s_prefix |= ((unsigned)tid) << shift;
                    s_target  = tgt - excl;
                }
                done_mask |= 0xFFu << shift;
                __syncthreads();
            }
            unsigned T = s_prefix;
            int r = s_target;
            int chunk = (ng + NT - 1) / NT;
            int lo = min(tid * chunk, ng);
            int hi = min(lo + chunk, ng);
            int cnt = 0;
            for (int t = lo; t < hi; ++t) cnt += (sm.tk.u[t] == T);
            int eqrank = scan256(cnt, tid, sm.tk.wsum);
            for (int t = lo; t < hi; ++t) {
                unsigned u = sm.tk.u[t];
                bool sel = (u < T) || (u == T && eqrank <= r);
                eqrank += (u == T);
                if (sel) atomicOr(&g_mask[start + t], 1 << c);
            }
        } else {
            for (int t = tid; t < ng; t += NT) {
                float st = __ldcg(&g_agg[(size_t)(start + t) * 4 + c]);
                int rank = 0;
                for (int j = 0; j < ng; ++j) {
                    float sj = __ldcg(&g_agg[(size_t)(start + j) * 4 + c]);
                    rank += (sj > st) || (sj == st && j < t);
                }
                if (rank < k) atomicOr(&g_mask[start + t], 1 << c);
            }
        }
        __syncthreads();
    }
    gbar();

    // ===== Phase 5: output (4 nodes/warp) ===================================
    for (int t = tid; t < CC * (INCH / 4); t += NT)
        sm.o.pe[t] = ((const float4*)pe)[t];
    __syncthreads();

    int outU = (n + 31) >> 5;
    for (int v = bid; v < outU; v += NB) {
        int base = v * 32 + warp * 4;
        int    mj[4];
        float4 sj[4];
        float4 xv[4][2];
#pragma unroll
        for (int j = 0; j < 4; ++j) {
            int node = (base + j < n) ? base + j : (n - 1);
            mj[j] = __ldcg(&g_mask[node]);
            sj[j] = __ldcg((const float4*)&g_agg[4 * node]);
            const float4* xr = (const float4*)(x + (size_t)node * INCH);
            xv[j][0] = __ldcs(&xr[lane]);
            xv[j][1] = __ldcs(&xr[lane + 32]);
        }
#pragma unroll
        for (int j = 0; j < 4; ++j) {
            if (base + j >= n) continue;
            int   m   = mj[j];
            float inv = 1.0f / (1.0f + (float)__popc(m & 0xF));
            float w0 = (m & 1) ? sj[j].x * inv : 0.f;
            float w1 = (m & 2) ? sj[j].y * inv : 0.f;
            float w2 = (m & 4) ? sj[j].z * inv : 0.f;
            float w3 = (m & 8) ? sj[j].w * inv : 0.f;
            float4* orow = (float4*)(out + (size_t)(base + j) * INCH);
#pragma unroll
            for (int it = 0; it < 2; ++it) {
                int k4 = lane + it * 32;
                float4 q  = xv[j][it];
                float4 p0 = sm.o.pe[0 * 64 + k4];
                float4 p1 = sm.o.pe[1 * 64 + k4];
                float4 p2 = sm.o.pe[2 * 64 + k4];
                float4 p3 = sm.o.pe[3 * 64 + k4];
                float4 o;
                o.x = q.x + w0 * p0.x + w1 * p1.x + w2 * p2.x + w3 * p3.x;
                o.y = q.y + w0 * p0.y + w1 * p1.y + w2 * p2.y + w3 * p3.y;
                o.z = q.z + w0 * p0.z + w1 * p1.z + w2 * p2.z + w3 * p3.z;
                o.w = q.w + w0 * p0.w + w1 * p1.w + w2 * p2.w + w3 * p3.w;
                __stcs(&orow[k4], o);
            }
        }
    }
}

// ---------------------------------------------------------------------------
extern "C" void kernel_launch(void* const* d_in, const int* in_sizes, int n_in,
                              void* d_out, int out_size) {
    const float* x     = (const float*)d_in[0];
    const int*   ei    = (const int*)  d_in[1];
    const int*   batch = (const int*)  d_in[2];
    const float* pe    = (const float*)d_in[3];
    const float* W     = (const float*)d_in[4];
    const float* b     = (const float*)d_in[5];
    float*       out   = (float*)d_out;

    int n = in_sizes[0] / INCH;
    int E = in_sizes[1] / 2;

    int dev = 0;
    cudaGetDevice(&dev);
    int smc = 0;
    if (cudaDeviceGetAttribute(&smc, cudaDevAttrMultiProcessorCount, dev)
            != cudaSuccess || smc <= 0)
        smc = 148;
    int NB = smc * 3;                     // all CTAs co-resident (launch_bounds 256,3)

    k_fused<<<NB, NT>>>(x, ei, batch, pe, W, b, out, n, E);
}